// round 4
// baseline (speedup 1.0000x reference)
#include <cuda_runtime.h>
#include <cuda_bf16.h>

// ---------------------------------------------------------------------------
// GATnet: 2-layer GAT. N=100000, E=1600000, IN=128, L1: 8 heads x 8 ch concat,
// ELU, L2: 1 head x 40, log_softmax.
// Strategy: fused GEMM+attention node kernels, single atomic edge pass per
// layer (deferred softmax division, self-loops in node kernels, no segment_max
// needed since logits are small). Edge-index dtype (int32 vs int64) detected
// on device and normalized to int32 scratch.
// ---------------------------------------------------------------------------

#define N_CAP 100000
#define E_CAP 1600000
#define IN_F  128
#define HC1   64     // 8 heads * 8 ch
#define H1    8
#define OUT2  40
#define NEG_SLOPE 0.2f

// Scratch (static device globals; ~110MB total)
__device__ float4 g_h1[N_CAP * 16];        // [N][64] as float4
__device__ float  g_asrc1[N_CAP * H1];
__device__ float  g_adst1[N_CAP * H1];
__device__ float  g_denom1[N_CAP * H1];
__device__ float4 g_out1[N_CAP * 16];      // [N][64]
__device__ float4 g_g2[N_CAP * 10];        // [N][40]
__device__ float  g_asrc2[N_CAP];
__device__ float  g_adst2[N_CAP];
__device__ float  g_denom2[N_CAP];
__device__ float4 g_out2[N_CAP * 10];      // [N][40]
__device__ int    g_src[E_CAP];
__device__ int    g_dst[E_CAP];
__device__ int    g_is64;

__device__ __forceinline__ void red_add_f32(float* addr, float v) {
    asm volatile("red.global.add.f32 [%0], %1;" :: "l"(addr), "f"(v) : "memory");
}
__device__ __forceinline__ void red_add_v4(float4* addr, float4 v) {
    asm volatile("red.global.add.v4.f32 [%0], {%1,%2,%3,%4};"
                 :: "l"(addr), "f"(v.x), "f"(v.y), "f"(v.z), "f"(v.w) : "memory");
}
__device__ __forceinline__ float lrelu(float v) { return v > 0.f ? v : NEG_SLOPE * v; }

// ---------------------------------------------------------------------------
// K0a: detect edge_index dtype. If stored as int64 (little-endian, ids < 2^31)
// the high word of every 8-byte element is 0. For int32 data the odd 4-byte
// words are random node ids (P(all zero) ~ 0).
// ---------------------------------------------------------------------------
__global__ void k0_detect(const unsigned int* ei32, int nwords) {
    __shared__ int any_nz;
    if (threadIdx.x == 0) any_nz = 0;
    __syncthreads();
    int samples = 2048;
    if (samples * 2 > nwords) samples = nwords / 2;
    for (int i = threadIdx.x; i < samples; i += 256)
        if (ei32[2 * i + 1] != 0u) any_nz = 1;
    __syncthreads();
    if (threadIdx.x == 0) g_is64 = (any_nz == 0) ? 1 : 0;
}

// K0b: normalize edge_index to int32 g_src/g_dst.
__global__ __launch_bounds__(256) void k0_convert(const void* ei, int E) {
    int i = blockIdx.x * 256 + threadIdx.x;
    if (i >= 2 * E) return;
    int v;
    if (g_is64) v = (int)((const long long*)ei)[i];
    else        v = ((const int*)ei)[i];
    if (i < E) g_src[i] = v;
    else       g_dst[i - E] = v;
}

// ---------------------------------------------------------------------------
// K1: h1 = x @ W1; a_src1/a_dst1 = h1 . att; self-loop init of denom1/out1.
// Block: 256 thr -> 128 nodes x 64 outs. Thread: 2 nodes x 16 outs.
// ---------------------------------------------------------------------------
__global__ __launch_bounds__(256) void k1_gemm_attn(
    const float* __restrict__ x, const float* __restrict__ W1,
    const float* __restrict__ atts, const float* __restrict__ attd, int N)
{
    __shared__ float Ws[IN_F * HC1];   // 32KB
    __shared__ float s_as[HC1], s_ad[HC1];
    for (int i = threadIdx.x; i < IN_F * HC1; i += 256) Ws[i] = W1[i];
    if (threadIdx.x < HC1) { s_as[threadIdx.x] = atts[threadIdx.x]; s_ad[threadIdx.x] = attd[threadIdx.x]; }
    __syncthreads();

    const int jq = threadIdx.x & 3;          // 0..3
    const int j0 = jq * 16;                  // channel base
    const int pr = threadIdx.x >> 2;         // 0..63
    const long long n0 = (long long)blockIdx.x * 128 + pr * 2;
    const long long n1 = n0 + 1;
    const bool v0 = n0 < N, v1 = n1 < N;

    const float4* xp0 = (const float4*)(x + (v0 ? n0 : 0) * IN_F);
    const float4* xp1 = (const float4*)(x + (v1 ? n1 : 0) * IN_F);

    float acc0[16], acc1[16];
#pragma unroll
    for (int i = 0; i < 16; i++) { acc0[i] = 0.f; acc1[i] = 0.f; }

#pragma unroll 8
    for (int k4 = 0; k4 < IN_F / 4; k4++) {
        float4 xa = xp0[k4];
        float4 xb = xp1[k4];
        const float* wrow = &Ws[k4 * 4 * HC1 + j0];
#pragma unroll
        for (int kk = 0; kk < 4; kk++) {
            float xav = (&xa.x)[kk];
            float xbv = (&xb.x)[kk];
#pragma unroll
            for (int jj = 0; jj < 4; jj++) {
                float4 w = *(const float4*)(wrow + kk * HC1 + jj * 4);
                acc0[jj*4+0] += xav * w.x; acc0[jj*4+1] += xav * w.y;
                acc0[jj*4+2] += xav * w.z; acc0[jj*4+3] += xav * w.w;
                acc1[jj*4+0] += xbv * w.x; acc1[jj*4+1] += xbv * w.y;
                acc1[jj*4+2] += xbv * w.z; acc1[jj*4+3] += xbv * w.w;
            }
        }
    }

    const int h0 = j0 >> 3;   // this thread fully owns heads h0, h0+1
#pragma unroll
    for (int sel = 0; sel < 2; sel++) {
        const bool valid = sel ? v1 : v0;
        if (!valid) continue;
        const long long n = sel ? n1 : n0;
        float* acc = sel ? acc1 : acc0;

        float as0 = 0.f, ad0 = 0.f, as1 = 0.f, ad1 = 0.f;
#pragma unroll
        for (int c = 0; c < 8; c++) {
            as0 += acc[c]     * s_as[h0 * 8 + c];
            ad0 += acc[c]     * s_ad[h0 * 8 + c];
            as1 += acc[8 + c] * s_as[(h0 + 1) * 8 + c];
            ad1 += acc[8 + c] * s_ad[(h0 + 1) * 8 + c];
        }
        float w0 = __expf(lrelu(as0 + ad0));
        float w1 = __expf(lrelu(as1 + ad1));

        g_asrc1[n * H1 + h0]     = as0;  g_asrc1[n * H1 + h0 + 1] = as1;
        g_adst1[n * H1 + h0]     = ad0;  g_adst1[n * H1 + h0 + 1] = ad1;
        g_denom1[n * H1 + h0]    = w0;   g_denom1[n * H1 + h0 + 1] = w1;

        float4* hp = &g_h1[n * 16 + jq * 4];
        float4* op = &g_out1[n * 16 + jq * 4];
#pragma unroll
        for (int q = 0; q < 4; q++) {
            float4 hv = make_float4(acc[q*4+0], acc[q*4+1], acc[q*4+2], acc[q*4+3]);
            float ww = (q < 2) ? w0 : w1;
            hp[q] = hv;
            op[q] = make_float4(hv.x * ww, hv.y * ww, hv.z * ww, hv.w * ww);
        }
    }
}

// ---------------------------------------------------------------------------
// K2: layer-1 edge pass. 8 lanes per edge (lane = head).
//   w = exp(lrelu(a_src[src,h] + a_dst[dst,h]))
//   denom1[dst,h] += w;  out1[dst,h,:] += w * h1[src,h,:]
// ---------------------------------------------------------------------------
__global__ __launch_bounds__(256) void k2_edges1(int E)
{
    const int t = blockIdx.x * 256 + threadIdx.x;
    const int e = t >> 3;
    const int r = t & 7;
    if (e >= E) return;
    const int src = g_src[e];
    const int dst = g_dst[e];

    float a = g_asrc1[src * H1 + r] + g_adst1[dst * H1 + r];
    float w = __expf(lrelu(a));
    red_add_f32(&g_denom1[dst * H1 + r], w);

    const float4* hs = &g_h1[(long long)src * 16 + r * 2];
    float4 v0 = hs[0], v1 = hs[1];
    float4* od = &g_out1[(long long)dst * 16 + r * 2];
    red_add_v4(od + 0, make_float4(v0.x * w, v0.y * w, v0.z * w, v0.w * w));
    red_add_v4(od + 1, make_float4(v1.x * w, v1.y * w, v1.z * w, v1.w * w));
}

// ---------------------------------------------------------------------------
// K4: per-node: h2 = elu(out1/denom1 + b1); g = h2 @ W2; a_src2/a_dst2;
//     self-loop init of denom2/out2. 8 threads per node (lane r: head r of h2,
//     output columns r, r+8, ..., r+32 of g).
// ---------------------------------------------------------------------------
__global__ __launch_bounds__(256) void k4_node2(
    const float* __restrict__ W2, const float* __restrict__ b1,
    const float* __restrict__ atts2, const float* __restrict__ attd2, int N)
{
    __shared__ float W2s[HC1 * OUT2];   // 10.2KB
    __shared__ float b1s[HC1], as2s[OUT2], ad2s[OUT2];
    for (int i = threadIdx.x; i < HC1 * OUT2; i += 256) W2s[i] = W2[i];
    if (threadIdx.x < HC1) b1s[threadIdx.x] = b1[threadIdx.x];
    if (threadIdx.x < OUT2) { as2s[threadIdx.x] = atts2[threadIdx.x]; ad2s[threadIdx.x] = attd2[threadIdx.x]; }
    __syncthreads();

    const int r = threadIdx.x & 7;
    const int n = blockIdx.x * 32 + (threadIdx.x >> 3);
    const int nc = (n < N) ? n : (N - 1);

    // h2 channels r*8 .. r*8+7 (== head r)
    float inv = 1.0f / g_denom1[(long long)nc * H1 + r];
    float4 o0 = g_out1[(long long)nc * 16 + r * 2];
    float4 o1 = g_out1[(long long)nc * 16 + r * 2 + 1];
    float h2r[8];
    {
        const float* bb = &b1s[r * 8];
        float tv[8] = { o0.x, o0.y, o0.z, o0.w, o1.x, o1.y, o1.z, o1.w };
#pragma unroll
        for (int c = 0; c < 8; c++) {
            float v = tv[c] * inv + bb[c];
            h2r[c] = v > 0.f ? v : expm1f(v);
        }
    }

    float acc[5] = {0.f, 0.f, 0.f, 0.f, 0.f};
#pragma unroll
    for (int k = 0; k < HC1; k++) {
        float hk = __shfl_sync(0xffffffffu, h2r[k & 7], k >> 3, 8);
#pragma unroll
        for (int i = 0; i < 5; i++) acc[i] += hk * W2s[k * OUT2 + r + 8 * i];
    }

    float as = 0.f, ad = 0.f;
#pragma unroll
    for (int i = 0; i < 5; i++) { as += acc[i] * as2s[r + 8 * i]; ad += acc[i] * ad2s[r + 8 * i]; }
#pragma unroll
    for (int o = 4; o; o >>= 1) {
        as += __shfl_xor_sync(0xffffffffu, as, o);
        ad += __shfl_xor_sync(0xffffffffu, ad, o);
    }
    float w = __expf(lrelu(as + ad));

    if (n < N) {
        if (r == 0) { g_asrc2[n] = as; g_adst2[n] = ad; g_denom2[n] = w; }
        float* gp = (float*)g_g2 + (long long)n * OUT2;
        float* op = (float*)g_out2 + (long long)n * OUT2;
#pragma unroll
        for (int i = 0; i < 5; i++) {
            gp[r + 8 * i] = acc[i];
            op[r + 8 * i] = acc[i] * w;
        }
    }
}

// ---------------------------------------------------------------------------
// K5: layer-2 edge pass. 16 lanes per edge; lanes 0..9 carry one float4 of g,
// lane 10 handles denom.
// ---------------------------------------------------------------------------
__global__ __launch_bounds__(256) void k5_edges2(int E)
{
    const int t = blockIdx.x * 256 + threadIdx.x;
    const int e = t >> 4;
    const int r = t & 15;
    if (e >= E || r > 10) return;
    const int src = g_src[e];
    const int dst = g_dst[e];

    float a = g_asrc2[src] + g_adst2[dst];
    float w = __expf(lrelu(a));
    if (r == 10) {
        red_add_f32(&g_denom2[dst], w);
    } else {
        float4 gv = g_g2[(long long)src * 10 + r];
        red_add_v4(&g_out2[(long long)dst * 10 + r],
                   make_float4(gv.x * w, gv.y * w, gv.z * w, gv.w * w));
    }
}

// ---------------------------------------------------------------------------
// K6: o = out2/denom2 + b2; log_softmax over 40. Warp per node.
// ---------------------------------------------------------------------------
__global__ __launch_bounds__(256) void k6_softmax(
    const float* __restrict__ b2, float* __restrict__ out, int N)
{
    const int lane = threadIdx.x & 31;
    const int n = blockIdx.x * 8 + (threadIdx.x >> 5);
    if (n >= N) return;
    float inv = 1.0f / g_denom2[n];
    const float* o2 = (const float*)g_out2 + (long long)n * OUT2;

    float v0 = o2[lane] * inv + b2[lane];
    float v1 = (lane < 8) ? (o2[32 + lane] * inv + b2[32 + lane]) : -3.0e38f;

    float m = fmaxf(v0, v1);
#pragma unroll
    for (int o = 16; o; o >>= 1) m = fmaxf(m, __shfl_xor_sync(0xffffffffu, m, o));
    float s = expf(v0 - m) + ((lane < 8) ? expf(v1 - m) : 0.f);
#pragma unroll
    for (int o = 16; o; o >>= 1) s += __shfl_xor_sync(0xffffffffu, s, o);
    float lse = m + logf(s);

    out[(long long)n * OUT2 + lane] = v0 - lse;
    if (lane < 8) out[(long long)n * OUT2 + 32 + lane] = v1 - lse;
}

// ---------------------------------------------------------------------------
extern "C" void kernel_launch(void* const* d_in, const int* in_sizes, int n_in,
                              void* d_out, int out_size)
{
    const float*     x      = (const float*)d_in[0];
    const void*      ei     = d_in[1];
    const float*     W1     = (const float*)d_in[2];
    const float*     atts1  = (const float*)d_in[3];
    const float*     attd1  = (const float*)d_in[4];
    const float*     b1     = (const float*)d_in[5];
    const float*     W2     = (const float*)d_in[6];
    const float*     atts2  = (const float*)d_in[7];
    const float*     attd2  = (const float*)d_in[8];
    const float*     b2     = (const float*)d_in[9];

    int N = in_sizes[0] / IN_F;
    int E = in_sizes[1] / 2;
    if (N > N_CAP) N = N_CAP;
    if (E > E_CAP) E = E_CAP;

    k0_detect<<<1, 256>>>((const unsigned int*)ei, 2 * E);
    k0_convert<<<(2 * E + 255) / 256, 256>>>(ei, E);
    k1_gemm_attn<<<(N + 127) / 128, 256>>>(x, W1, atts1, attd1, N);
    k2_edges1<<<(E * 8 + 255) / 256, 256>>>(E);
    k4_node2<<<(N + 31) / 32, 256>>>(W2, b1, atts2, attd2, N);
    k5_edges2<<<(int)(((long long)E * 16 + 255) / 256), 256>>>(E);
    k6_softmax<<<(N + 7) / 8, 256>>>(b2, (float*)d_out, N);
}

// round 5
// speedup vs baseline: 1.5077x; 1.5077x over previous
#include <cuda_runtime.h>
#include <cuda_bf16.h>

// ---------------------------------------------------------------------------
// GATnet 2-layer GAT, N=100000, E=1600000, IN=128, L1: 8x8 concat, ELU,
// L2: 1x40, log_softmax.
// R5: device-built CSR by destination; gather-based (atomic-free) edge
// aggregation with register accumulators; layer-1 aggregate fused with the
// layer-2 node transform; layer-2 aggregate fused with log_softmax.
// ---------------------------------------------------------------------------

#define N_CAP 100000
#define E_CAP 1600000
#define IN_F  128
#define HC1   64
#define H1    8
#define OUT2  40
#define NEG_SLOPE 0.2f

// Scratch (static device globals)
__device__ float4 g_h1[N_CAP * 16];        // [N][64]
__device__ float  g_asrc1[N_CAP * H1];
__device__ float  g_adst1[N_CAP * H1];
__device__ float  g_g2[N_CAP * OUT2];      // [N][40]
__device__ float  g_asrc2[N_CAP];
__device__ float  g_adst2[N_CAP];
__device__ int    g_esrc[E_CAP];           // CSR: src ids grouped by dst
__device__ int    g_deg[N_CAP];
__device__ int    g_rowptr[N_CAP];
__device__ int    g_cursor[N_CAP];
__device__ int    g_blksum[256];
__device__ int    g_is64;

__device__ __forceinline__ float lrelu(float v) { return v > 0.f ? v : NEG_SLOPE * v; }

// ---------------------------------------------------------------------------
// CSR construction
// ---------------------------------------------------------------------------
__global__ void k0_detect(const unsigned int* ei32, int nwords) {
    __shared__ int any_nz;
    if (threadIdx.x == 0) any_nz = 0;
    __syncthreads();
    int samples = 2048;
    if (samples * 2 > nwords) samples = nwords / 2;
    for (int i = threadIdx.x; i < samples; i += 256)
        if (ei32[2 * i + 1] != 0u) any_nz = 1;
    __syncthreads();
    if (threadIdx.x == 0) g_is64 = (any_nz == 0) ? 1 : 0;
}

__global__ __launch_bounds__(256) void k_zero(int N) {
    int i = blockIdx.x * 256 + threadIdx.x;
    if (i < N) g_deg[i] = 0;
}

__global__ __launch_bounds__(256) void k_hist(const void* ei, int E) {
    int i = blockIdx.x * 256 + threadIdx.x;
    if (i >= E) return;
    int dst = g_is64 ? (int)((const long long*)ei)[E + i] : ((const int*)ei)[E + i];
    atomicAdd(&g_deg[dst], 1);
}

__global__ __launch_bounds__(512) void k_scan1(int N) {
    __shared__ int s[512];
    int i = blockIdx.x * 512 + threadIdx.x;
    int v = (i < N) ? g_deg[i] : 0;
    s[threadIdx.x] = v;
    __syncthreads();
#pragma unroll
    for (int off = 1; off < 512; off <<= 1) {
        int t = (threadIdx.x >= off) ? s[threadIdx.x - off] : 0;
        __syncthreads();
        s[threadIdx.x] += t;
        __syncthreads();
    }
    if (i < N) g_rowptr[i] = s[threadIdx.x] - v;   // exclusive
    if (threadIdx.x == 511) g_blksum[blockIdx.x] = s[511];
}

__global__ void k_scan2(int nb) {
    if (threadIdx.x == 0) {
        int run = 0;
        for (int b = 0; b < nb; b++) { int t = g_blksum[b]; g_blksum[b] = run; run += t; }
    }
}

__global__ __launch_bounds__(256) void k_scan3(int N) {
    int i = blockIdx.x * 256 + threadIdx.x;
    if (i >= N) return;
    int r = g_rowptr[i] + g_blksum[i >> 9];
    g_rowptr[i] = r;
    g_cursor[i] = r;
}

__global__ __launch_bounds__(256) void k_scatter(const void* ei, int E) {
    int i = blockIdx.x * 256 + threadIdx.x;
    if (i >= E) return;
    int src, dst;
    if (g_is64) {
        src = (int)((const long long*)ei)[i];
        dst = (int)((const long long*)ei)[E + i];
    } else {
        src = ((const int*)ei)[i];
        dst = ((const int*)ei)[E + i];
    }
    int pos = atomicAdd(&g_cursor[dst], 1);
    g_esrc[pos] = src;
}

// ---------------------------------------------------------------------------
// K1: h1 = x @ W1; a_src1/a_dst1 = h1 . att.
// ---------------------------------------------------------------------------
__global__ __launch_bounds__(256) void k1_gemm_attn(
    const float* __restrict__ x, const float* __restrict__ W1,
    const float* __restrict__ atts, const float* __restrict__ attd, int N)
{
    __shared__ float Ws[IN_F * HC1];   // 32KB
    __shared__ float s_as[HC1], s_ad[HC1];
    for (int i = threadIdx.x; i < IN_F * HC1; i += 256) Ws[i] = W1[i];
    if (threadIdx.x < HC1) { s_as[threadIdx.x] = atts[threadIdx.x]; s_ad[threadIdx.x] = attd[threadIdx.x]; }
    __syncthreads();

    const int jq = threadIdx.x & 3;
    const int j0 = jq * 16;
    const int pr = threadIdx.x >> 2;
    const long long n0 = (long long)blockIdx.x * 128 + pr * 2;
    const long long n1 = n0 + 1;
    const bool v0 = n0 < N, v1 = n1 < N;

    const float4* xp0 = (const float4*)(x + (v0 ? n0 : 0) * IN_F);
    const float4* xp1 = (const float4*)(x + (v1 ? n1 : 0) * IN_F);

    float acc0[16], acc1[16];
#pragma unroll
    for (int i = 0; i < 16; i++) { acc0[i] = 0.f; acc1[i] = 0.f; }

#pragma unroll 8
    for (int k4 = 0; k4 < IN_F / 4; k4++) {
        float4 xa = xp0[k4];
        float4 xb = xp1[k4];
        const float* wrow = &Ws[k4 * 4 * HC1 + j0];
#pragma unroll
        for (int kk = 0; kk < 4; kk++) {
            float xav = (&xa.x)[kk];
            float xbv = (&xb.x)[kk];
#pragma unroll
            for (int jj = 0; jj < 4; jj++) {
                float4 w = *(const float4*)(wrow + kk * HC1 + jj * 4);
                acc0[jj*4+0] += xav * w.x; acc0[jj*4+1] += xav * w.y;
                acc0[jj*4+2] += xav * w.z; acc0[jj*4+3] += xav * w.w;
                acc1[jj*4+0] += xbv * w.x; acc1[jj*4+1] += xbv * w.y;
                acc1[jj*4+2] += xbv * w.z; acc1[jj*4+3] += xbv * w.w;
            }
        }
    }

    const int h0 = j0 >> 3;
#pragma unroll
    for (int sel = 0; sel < 2; sel++) {
        const bool valid = sel ? v1 : v0;
        if (!valid) continue;
        const long long n = sel ? n1 : n0;
        float* acc = sel ? acc1 : acc0;

        float as0 = 0.f, ad0 = 0.f, as1 = 0.f, ad1 = 0.f;
#pragma unroll
        for (int c = 0; c < 8; c++) {
            as0 += acc[c]     * s_as[h0 * 8 + c];
            ad0 += acc[c]     * s_ad[h0 * 8 + c];
            as1 += acc[8 + c] * s_as[(h0 + 1) * 8 + c];
            ad1 += acc[8 + c] * s_ad[(h0 + 1) * 8 + c];
        }
        g_asrc1[n * H1 + h0]     = as0;  g_asrc1[n * H1 + h0 + 1] = as1;
        g_adst1[n * H1 + h0]     = ad0;  g_adst1[n * H1 + h0 + 1] = ad1;

        float4* hp = &g_h1[n * 16 + jq * 4];
#pragma unroll
        for (int q = 0; q < 4; q++)
            hp[q] = make_float4(acc[q*4+0], acc[q*4+1], acc[q*4+2], acc[q*4+3]);
    }
}

// ---------------------------------------------------------------------------
// KL1: fused layer-1 aggregate (gather, register acc) + softmax normalize +
//      ELU + h2@W2 + layer-2 attention scalars. 8 lanes per node (lane=head).
// ---------------------------------------------------------------------------
__global__ __launch_bounds__(256) void kL1_gather(
    const float* __restrict__ W2, const float* __restrict__ b1,
    const float* __restrict__ atts2, const float* __restrict__ attd2, int N)
{
    __shared__ float W2s[HC1 * OUT2];   // 10.2KB
    __shared__ float b1s[HC1], as2s[OUT2], ad2s[OUT2];
    for (int i = threadIdx.x; i < HC1 * OUT2; i += 256) W2s[i] = W2[i];
    if (threadIdx.x < HC1) b1s[threadIdx.x] = b1[threadIdx.x];
    if (threadIdx.x < OUT2) { as2s[threadIdx.x] = atts2[threadIdx.x]; ad2s[threadIdx.x] = attd2[threadIdx.x]; }
    __syncthreads();

    const int r = threadIdx.x & 7;
    const int n = blockIdx.x * 32 + (threadIdx.x >> 3);
    const int nc = (n < N) ? n : 0;

    const float adst = g_adst1[nc * H1 + r];
    const int beg = g_rowptr[nc];
    const int end = beg + g_deg[nc];

    // self-loop
    float w = __expf(lrelu(g_asrc1[nc * H1 + r] + adst));
    float denom = w;
    float4 a0 = g_h1[(long long)nc * 16 + r * 2];
    float4 a1 = g_h1[(long long)nc * 16 + r * 2 + 1];
    float acc[8] = { w*a0.x, w*a0.y, w*a0.z, w*a0.w, w*a1.x, w*a1.y, w*a1.z, w*a1.w };

    for (int p = beg; p < end; p++) {
        int src = g_esrc[p];
        float wi = __expf(lrelu(g_asrc1[src * H1 + r] + adst));
        denom += wi;
        float4 v0 = g_h1[(long long)src * 16 + r * 2];
        float4 v1 = g_h1[(long long)src * 16 + r * 2 + 1];
        acc[0] += wi * v0.x; acc[1] += wi * v0.y; acc[2] += wi * v0.z; acc[3] += wi * v0.w;
        acc[4] += wi * v1.x; acc[5] += wi * v1.y; acc[6] += wi * v1.z; acc[7] += wi * v1.w;
    }

    // h2 = elu(acc/denom + b1)
    float inv = 1.0f / denom;
    float h2r[8];
    {
        const float* bb = &b1s[r * 8];
#pragma unroll
        for (int c = 0; c < 8; c++) {
            float v = acc[c] * inv + bb[c];
            h2r[c] = v > 0.f ? v : expm1f(v);
        }
    }

    // g = h2 @ W2 (8-lane shuffle GEMM); lane r owns cols r, r+8, ..., r+32
    float acc2[5] = {0.f, 0.f, 0.f, 0.f, 0.f};
#pragma unroll
    for (int k = 0; k < HC1; k++) {
        float hk = __shfl_sync(0xffffffffu, h2r[k & 7], k >> 3, 8);
#pragma unroll
        for (int i = 0; i < 5; i++) acc2[i] += hk * W2s[k * OUT2 + r + 8 * i];
    }

    float as = 0.f, ad = 0.f;
#pragma unroll
    for (int i = 0; i < 5; i++) { as += acc2[i] * as2s[r + 8 * i]; ad += acc2[i] * ad2s[r + 8 * i]; }
#pragma unroll
    for (int o = 4; o; o >>= 1) {
        as += __shfl_xor_sync(0xffffffffu, as, o, 8);
        ad += __shfl_xor_sync(0xffffffffu, ad, o, 8);
    }

    if (n < N) {
        if (r == 0) { g_asrc2[n] = as; g_adst2[n] = ad; }
        float* gp = g_g2 + (long long)n * OUT2;
#pragma unroll
        for (int i = 0; i < 5; i++) gp[r + 8 * i] = acc2[i];
    }
}

// ---------------------------------------------------------------------------
// KL2: fused layer-2 aggregate (gather) + normalize + bias + log_softmax.
//      16 lanes per node; lanes 0..9 each own one float4 of the 40 outputs.
// ---------------------------------------------------------------------------
__global__ __launch_bounds__(256) void kL2_gather(
    const float* __restrict__ b2, float* __restrict__ out, int N)
{
    const int r = threadIdx.x & 15;
    const int n = blockIdx.x * 16 + (threadIdx.x >> 4);
    const int nc = (n < N) ? n : 0;
    const bool act = (r < 10);

    const float adst = g_adst2[nc];
    const int beg = g_rowptr[nc];
    const int end = beg + g_deg[nc];

    // self-loop
    float w = __expf(lrelu(g_asrc2[nc] + adst));
    float denom = w;
    float4 acc = make_float4(0.f, 0.f, 0.f, 0.f);
    if (act) {
        float4 g = ((const float4*)(g_g2 + (long long)nc * OUT2))[r];
        acc = make_float4(w * g.x, w * g.y, w * g.z, w * g.w);
    }

    for (int p = beg; p < end; p++) {
        int src = g_esrc[p];
        float wi = __expf(lrelu(g_asrc2[src] + adst));
        denom += wi;
        if (act) {
            float4 g = ((const float4*)(g_g2 + (long long)src * OUT2))[r];
            acc.x += wi * g.x; acc.y += wi * g.y; acc.z += wi * g.z; acc.w += wi * g.w;
        }
    }

    float inv = 1.0f / denom;
    float4 v = make_float4(-3.0e38f, -3.0e38f, -3.0e38f, -3.0e38f);
    if (act) {
        float4 bb = ((const float4*)b2)[r];
        v = make_float4(acc.x * inv + bb.x, acc.y * inv + bb.y,
                        acc.z * inv + bb.z, acc.w * inv + bb.w);
    }

    // log_softmax across the 10 active lanes (width-16 reductions)
    float m = fmaxf(fmaxf(v.x, v.y), fmaxf(v.z, v.w));
#pragma unroll
    for (int o = 8; o; o >>= 1) m = fmaxf(m, __shfl_xor_sync(0xffffffffu, m, o, 16));
    float s = 0.f;
    if (act) s = expf(v.x - m) + expf(v.y - m) + expf(v.z - m) + expf(v.w - m);
#pragma unroll
    for (int o = 8; o; o >>= 1) s += __shfl_xor_sync(0xffffffffu, s, o, 16);
    float lse = m + logf(s);

    if (act && n < N) {
        float4 o4 = make_float4(v.x - lse, v.y - lse, v.z - lse, v.w - lse);
        ((float4*)(out + (long long)n * OUT2))[r] = o4;
    }
}

// ---------------------------------------------------------------------------
extern "C" void kernel_launch(void* const* d_in, const int* in_sizes, int n_in,
                              void* d_out, int out_size)
{
    const float* x     = (const float*)d_in[0];
    const void*  ei    = d_in[1];
    const float* W1    = (const float*)d_in[2];
    const float* atts1 = (const float*)d_in[3];
    const float* attd1 = (const float*)d_in[4];
    const float* b1    = (const float*)d_in[5];
    const float* W2    = (const float*)d_in[6];
    const float* atts2 = (const float*)d_in[7];
    const float* attd2 = (const float*)d_in[8];
    const float* b2    = (const float*)d_in[9];

    int N = in_sizes[0] / IN_F;
    int E = in_sizes[1] / 2;
    if (N > N_CAP) N = N_CAP;
    if (E > E_CAP) E = E_CAP;
    const int nb_scan = (N + 511) / 512;

    k0_detect<<<1, 256>>>((const unsigned int*)ei, 2 * E);
    k_zero<<<(N + 255) / 256, 256>>>(N);
    k_hist<<<(E + 255) / 256, 256>>>(ei, E);
    k_scan1<<<nb_scan, 512>>>(N);
    k_scan2<<<1, 32>>>(nb_scan);
    k_scan3<<<(N + 255) / 256, 256>>>(N);
    k_scatter<<<(E + 255) / 256, 256>>>(ei, E);

    k1_gemm_attn<<<(N + 127) / 128, 256>>>(x, W1, atts1, attd1, N);
    kL1_gather<<<(N + 31) / 32, 256>>>(W2, b1, atts2, attd2, N);
    kL2_gather<<<(N + 15) / 16, 256>>>(b2, (float*)d_out, N);
}